// round 15
// baseline (speedup 1.0000x reference)
#include <cuda_runtime.h>
#include <cuda_bf16.h>
#include <math.h>
#include <stdint.h>

// ---------------------------------------------------------------------------
// Model dims
// ---------------------------------------------------------------------------
#define B_      64
#define N_      512
#define D_      256
#define H_      4
#define HD_     64
#define M_      (B_ * N_)         // 32768 rows
#define EPS_    1e-5f

// ---------------------------------------------------------------------------
// Scratch: fp32 staging + pair-plane (hi 128 words | lo 128 words per row)
// ---------------------------------------------------------------------------
__device__ float    g_xp  [M_ * D_];
__device__ float    g_yp  [M_ * D_];
__device__ float    g_v   [M_ * D_];
__device__ float    g_xres[M_ * D_];
__device__ float    g_xmlp[M_ * D_];
__device__ float    g_pe  [N_ * D_];
__device__ uint32_t g_xpP [M_ * D_];
__device__ uint32_t g_ypP [M_ * D_];
__device__ uint32_t g_qP  [M_ * D_];
__device__ uint32_t g_kP  [M_ * D_];
__device__ uint32_t g_ctxP[M_ * D_];
__device__ uint32_t g_xrsP[M_ * D_];
__device__ uint32_t g_hidP[M_ * D_];

// bf16 hi/lo weight scratch (chunk-interleaved: 16 hi words, 16 lo words / 32k)
#define WR_OFF  0
#define WF_OFF  (WR_OFF + 256 * 800)
#define WQ_OFF  (WF_OFF + 256 * 704)
#define WK_OFF  (WQ_OFF + 256 * 256)
#define WV_OFF  (WK_OFF + 256 * 256)
#define WO_OFF  (WV_OFF + 256 * 256)
#define W1_OFF  (WO_OFF + 256 * 256)
#define W2_OFF  (W1_OFF + 256 * 256)
#define WB_TOT  (W2_OFF + 256 * 256)
__device__ uint32_t g_wbuf[WB_TOT];

// ---------------------------------------------------------------------------
__device__ __forceinline__ uint32_t hi_pair(float x0, float x1) {
    uint32_t a = __float_as_uint(x0), b = __float_as_uint(x1);
    return (b & 0xffff0000u) | (a >> 16);
}
__device__ __forceinline__ uint32_t lo_pair(float x0, float x1) {
    float l0 = x0 - __uint_as_float(__float_as_uint(x0) & 0xffff0000u);
    float l1 = x1 - __uint_as_float(__float_as_uint(x1) & 0xffff0000u);
    uint32_t a = (uint32_t)__bfloat16_as_ushort(__float2bfloat16(l0));
    uint32_t b = (uint32_t)__bfloat16_as_ushort(__float2bfloat16(l1));
    return (b << 16) | a;
}

__device__ __forceinline__ uint32_t smem_u32(const void* p) {
    uint32_t a;
    asm("{ .reg .u64 t; cvta.to.shared.u64 t, %1; cvt.u32.u64 %0, t; }"
        : "=r"(a) : "l"(p));
    return a;
}

#define LDMX4(r0, r1, r2, r3, addr) \
    asm volatile("ldmatrix.sync.aligned.m8n8.x4.shared.b16 {%0,%1,%2,%3}, [%4];" \
                 : "=r"(r0), "=r"(r1), "=r"(r2), "=r"(r3) : "r"(addr))

#define MMA_BF16(c, a, b0, b1) \
    asm volatile("mma.sync.aligned.m16n8k16.row.col.f32.bf16.bf16.f32 " \
                 "{%0,%1,%2,%3}, {%4,%5,%6,%7}, {%8,%9}, {%0,%1,%2,%3};" \
                 : "+f"((c)[0]), "+f"((c)[1]), "+f"((c)[2]), "+f"((c)[3]) \
                 : "r"((a)[0]), "r"((a)[1]), "r"((a)[2]), "r"((a)[3]), \
                   "r"(b0), "r"(b1))

#define CPASYNC16(dst, src) \
    asm volatile("cp.async.cg.shared.global [%0], [%1], 16;" \
                 :: "r"(dst), "l"(src))
#define CPASYNC_COMMIT()  asm volatile("cp.async.commit_group;" ::: "memory")
#define CPASYNC_WAIT0()   asm volatile("cp.async.wait_group 0;" ::: "memory")

// fast 2^x for x <= 0; rel err ~1.5e-5; no MUFU
__device__ __forceinline__ float fexp2(float x) {
    x = fmaxf(x, -80.0f);
    float n = floorf(x);
    float f = x - n;
    float p = 1.5404e-4f;
    p = fmaf(p, f, 1.333356e-3f);
    p = fmaf(p, f, 9.618130e-3f);
    p = fmaf(p, f, 5.550411e-2f);
    p = fmaf(p, f, 2.402265e-1f);
    p = fmaf(p, f, 6.931472e-1f);
    p = fmaf(p, f, 1.0f);
    return __int_as_float(__float_as_int(p) + ((int)n << 23));
}

// ---------------------------------------------------------------------------
// Prologue: weight hi/lo conversion + PE table
// ---------------------------------------------------------------------------
__global__ void prep_kernel(const float* __restrict__ Wr, const float* __restrict__ Wf,
                            const float* __restrict__ Wq, const float* __restrict__ Wk,
                            const float* __restrict__ Wv, const float* __restrict__ Wo,
                            const float* __restrict__ W1, const float* __restrict__ W2) {
    int idx = blockIdx.x * blockDim.x + threadIdx.x;
    if (idx < WB_TOT) {
        const float* W; int K, rowU32, base;
        if      (idx < WF_OFF) { W = Wr; K = 769; rowU32 = 800; base = WR_OFF; }
        else if (idx < WQ_OFF) { W = Wf; K = 674; rowU32 = 704; base = WF_OFF; }
        else if (idx < WK_OFF) { W = Wq; K = 256; rowU32 = 256; base = WQ_OFF; }
        else if (idx < WV_OFF) { W = Wk; K = 256; rowU32 = 256; base = WK_OFF; }
        else if (idx < WO_OFF) { W = Wv; K = 256; rowU32 = 256; base = WV_OFF; }
        else if (idx < W1_OFF) { W = Wo; K = 256; rowU32 = 256; base = WO_OFF; }
        else if (idx < W2_OFF) { W = W1; K = 256; rowU32 = 256; base = W1_OFF; }
        else                   { W = W2; K = 256; rowU32 = 256; base = W2_OFF; }
        int j   = idx - base;
        int row = j / rowU32;
        int jj  = j - row * rowU32;
        int c   = jj >> 5;
        int t   = jj & 31;
        int e0  = c * 32 + ((t & 15) << 1);
        float v0 = (e0     < K) ? W[(size_t)row * K + e0]     : 0.0f;
        float v1 = (e0 + 1 < K) ? W[(size_t)row * K + e0 + 1] : 0.0f;
        g_wbuf[idx] = (t < 16) ? hi_pair(v0, v1) : lo_pair(v0, v1);
    } else if (idx < WB_TOT + N_ * D_) {
        int j   = idx - WB_TOT;
        int pos = j >> 8;
        int c   = j & 255;
        int i2  = c & ~1;
        float div = expf(-logf(10000.0f) * (float)i2 / (float)D_);
        float ang = (float)pos * div;
        g_pe[j] = (c & 1) ? cosf(ang) : sinf(ang);
    }
}

// ---------------------------------------------------------------------------
// Row LayerNorm: warp per 256-col row. Optional fp32 write-back + pair output.
// ---------------------------------------------------------------------------
__global__ __launch_bounds__(256) void ln_kernel(
    float* __restrict__ io,
    const float* __restrict__ gamma,
    const float* __restrict__ beta,
    int writeF,
    uint32_t* __restrict__ outP)
{
    const int row  = blockIdx.x * 8 + (threadIdx.x >> 5);
    const int lane = threadIdx.x & 31;
    float* p = io + (size_t)row * D_ + lane * 8;
    float4 a = *(float4*)p;
    float4 b = *(float4*)(p + 4);
    float s = a.x + a.y + a.z + a.w + b.x + b.y + b.z + b.w;
    float q = a.x*a.x + a.y*a.y + a.z*a.z + a.w*a.w
            + b.x*b.x + b.y*b.y + b.z*b.z + b.w*b.w;
#pragma unroll
    for (int off = 16; off > 0; off >>= 1) {
        s += __shfl_xor_sync(0xffffffffu, s, off);
        q += __shfl_xor_sync(0xffffffffu, q, off);
    }
    float mu  = s * (1.0f / 256.0f);
    float var = q * (1.0f / 256.0f) - mu * mu;
    float rs  = rsqrtf(var + EPS_);
    const float* gp = gamma + lane * 8;
    const float* bp = beta  + lane * 8;
    float4 g0 = *(const float4*)gp,  g1 = *(const float4*)(gp + 4);
    float4 b0 = *(const float4*)bp,  b1 = *(const float4*)(bp + 4);
    a.x = (a.x - mu) * rs * g0.x + b0.x;  a.y = (a.y - mu) * rs * g0.y + b0.y;
    a.z = (a.z - mu) * rs * g0.z + b0.z;  a.w = (a.w - mu) * rs * g0.w + b0.w;
    b.x = (b.x - mu) * rs * g1.x + b1.x;  b.y = (b.y - mu) * rs * g1.y + b1.y;
    b.z = (b.z - mu) * rs * g1.z + b1.z;  b.w = (b.w - mu) * rs * g1.w + b1.w;
    if (writeF) {
        *(float4*)p       = a;
        *(float4*)(p + 4) = b;
    }
    uint4 hw = make_uint4(hi_pair(a.x, a.y), hi_pair(a.z, a.w),
                          hi_pair(b.x, b.y), hi_pair(b.z, b.w));
    uint4 lw = make_uint4(lo_pair(a.x, a.y), lo_pair(a.z, a.w),
                          lo_pair(b.x, b.y), lo_pair(b.z, b.w));
    *(uint4*)(outP + (size_t)row * 256 + lane * 4)       = hw;
    *(uint4*)(outP + (size_t)row * 256 + 128 + lane * 4) = lw;
}

// ---------------------------------------------------------------------------
// hmma_gemm_n128: 64x128 tile, 3 CTAs/SM, warp tile 32x32, generalized K.
// APAIR=1: A staged via cp.async from pair-plane buffer. gridDim.y picks set.
// EPI: 0=+bias 1=relu(+bias) 2=+bias+res 4=+bias+pe
// ---------------------------------------------------------------------------
#define ROWB     144
#define ABUF_S   (64 * ROWB)
#define BBUF_S   (128 * ROWB)
#define BUFSZ_S  (ABUF_S + BBUF_S)
#define SM_TOT_S (2 * BUFSZ_S)

template <int EPI, int APAIR>
__global__ __launch_bounds__(256, 3) void hmma_gemm_n128(
    const float* __restrict__ A, const uint32_t* __restrict__ Ap,
    int K, int NC,
    const uint32_t* __restrict__ Wbf, int rowU32, int wstride,
    const float* __restrict__ bias, const float* __restrict__ bias2,
    const float* __restrict__ res,
    const float* __restrict__ pe, float scale,
    float* __restrict__ outF, float* __restrict__ outF2,
    uint32_t* __restrict__ outP, uint32_t* __restrict__ outP2)
{
    extern __shared__ __align__(16) char sm[];
    const uint32_t smb = smem_u32(sm);
    const int tid  = threadIdx.x;
    const int lane = tid & 31;
    const int warp = tid >> 5;
    const int wr   = warp >> 2;
    const int wc   = warp & 3;
    const int ch   = blockIdx.x & 1;
    const int row0 = (blockIdx.x >> 1) * 64;

    const float* biasS = blockIdx.y ? bias2 : bias;
    float*       oF    = blockIdx.y ? outF2 : outF;
    uint32_t*    oP    = blockIdx.y ? outP2 : outP;

    const int arow = tid >> 2;
    const int aq   = tid & 3;
    const float*    Apf = A  ? A  + (size_t)(row0 + arow) * K + aq * 8 : nullptr;
    const uint32_t* App = Ap ? Ap + (size_t)(row0 + arow) * K : nullptr;
    const int brow = tid >> 1;
    const int bhf  = tid & 1;
    const uint32_t* Wp = Wbf + (size_t)blockIdx.y * wstride
                       + (size_t)(ch * 128 + brow) * rowU32;

    float acc[2][4][4];
#pragma unroll
    for (int mt = 0; mt < 2; ++mt)
#pragma unroll
        for (int nt = 0; nt < 4; ++nt)
#pragma unroll
            for (int i = 0; i < 4; ++i) acc[mt][nt][i] = 0.0f;

    const uint32_t a_rel = (uint32_t)(wr * 32 + (lane & 15)) * ROWB
                         + (uint32_t)(lane >> 4) * 16;
    const uint32_t b_rel = ABUF_S
                         + (uint32_t)(wc * 32 + ((lane >> 4) << 3) + (lane & 7)) * ROWB
                         + (uint32_t)((lane >> 3) & 1) * 16;

    auto ldgA = [&](int c, float* f) {
#pragma unroll
        for (int j = 0; j < 8; ++j) {
            int kg = c * 32 + aq * 8 + j;
            f[j] = (kg < K) ? Apf[c * 32 + j] : 0.0f;
        }
    };
    auto stsA = [&](const float* f, int p) {
        uint32_t hw[4], lw[4];
#pragma unroll
        for (int w = 0; w < 4; ++w) {
            hw[w] = hi_pair(f[2*w], f[2*w+1]);
            lw[w] = lo_pair(f[2*w], f[2*w+1]);
        }
        char* dh = sm + p * BUFSZ_S + arow * ROWB + aq * 16;
        *(uint4*)dh        = make_uint4(hw[0], hw[1], hw[2], hw[3]);
        *(uint4*)(dh + 64) = make_uint4(lw[0], lw[1], lw[2], lw[3]);
    };
    auto cpA = [&](int c, int p) {
        uint32_t dst = smb + p * BUFSZ_S + arow * ROWB + aq * 16;
        const char* srcH = (const char*)(App + c * 16 + aq * 4);
        const char* srcL = (const char*)(App + (K >> 1) + c * 16 + aq * 4);
        CPASYNC16(dst, srcH);
        CPASYNC16(dst + 64, srcL);
    };
    auto cpB = [&](int c, int p) {
        uint32_t dst = smb + p * BUFSZ_S + ABUF_S + brow * ROWB + bhf * 64;
        const char* src = (const char*)(Wp + c * 32 + bhf * 16);
#pragma unroll
        for (int g2 = 0; g2 < 4; ++g2)
            CPASYNC16(dst + g2 * 16, src + g2 * 16);
    };

    if (APAIR) {
        cpA(0, 0); cpB(0, 0);
        CPASYNC_COMMIT();
        CPASYNC_WAIT0();
    } else {
        float f0[8];
        ldgA(0, f0);
        cpB(0, 0);
        CPASYNC_COMMIT();
        stsA(f0, 0);
        CPASYNC_WAIT0();
    }
    __syncthreads();

    int p = 0;
    for (int c = 0; c < NC; ++c) {
        const bool have = (c + 1 < NC);
        float fn[8];
        if (have) {
            if (APAIR) { cpA(c + 1, p ^ 1); cpB(c + 1, p ^ 1); CPASYNC_COMMIT(); }
            else       { cpB(c + 1, p ^ 1); CPASYNC_COMMIT(); ldgA(c + 1, fn); }
        }
        const uint32_t ab = smb + p * BUFSZ_S + a_rel;
        const uint32_t bb = smb + p * BUFSZ_S + b_rel;
#pragma unroll
        for (int ks = 0; ks < 2; ++ks) {
            uint32_t ah[2][4], al[2][4];
#pragma unroll
            for (int mt = 0; mt < 2; ++mt) {
                LDMX4(ah[mt][0], ah[mt][1], ah[mt][2], ah[mt][3],
                      ab + mt * (16 * ROWB) + ks * 32);
                LDMX4(al[mt][0], al[mt][1], al[mt][2], al[mt][3],
                      ab + mt * (16 * ROWB) + ks * 32 + 64);
            }
            uint32_t bh0[4], bl0[4], bh1[4], bl1[4];
            LDMX4(bh0[0], bh0[1], bh0[2], bh0[3], bb + ks * 32);
            LDMX4(bl0[0], bl0[1], bl0[2], bl0[3], bb + ks * 32 + 64);
            LDMX4(bh1[0], bh1[1], bh1[2], bh1[3], bb + 16 * ROWB + ks * 32);
            LDMX4(bl1[0], bl1[1], bl1[2], bl1[3], bb + 16 * ROWB + ks * 32 + 64);
            // term 1
            MMA_BF16(acc[0][0], ah[0], bh0[0], bh0[1]);
            MMA_BF16(acc[1][0], ah[1], bh0[0], bh0[1]);
            MMA_BF16(acc[0][1], ah[0], bh0[2], bh0[3]);
            MMA_BF16(acc[1][1], ah[1], bh0[2], bh0[3]);
            MMA_BF16(acc[0][2], ah[0], bh1[0], bh1[1]);
            MMA_BF16(acc[1][2], ah[1], bh1[0], bh1[1]);
            MMA_BF16(acc[0][3], ah[0], bh1[2], bh1[3]);
            MMA_BF16(acc[1][3], ah[1], bh1[2], bh1[3]);
            // term 2
            MMA_BF16(acc[0][0], al[0], bh0[0], bh0[1]);
            MMA_BF16(acc[1][0], al[1], bh0[0], bh0[1]);
            MMA_BF16(acc[0][1], al[0], bh0[2], bh0[3]);
            MMA_BF16(acc[1][1], al[1], bh0[2], bh0[3]);
            MMA_BF16(acc[0][2], al[0], bh1[0], bh1[1]);
            MMA_BF16(acc[1][2], al[1], bh1[0], bh1[1]);
            MMA_BF16(acc[0][3], al[0], bh1[2], bh1[3]);
            MMA_BF16(acc[1][3], al[1], bh1[2], bh1[3]);
            // term 3
            MMA_BF16(acc[0][0], ah[0], bl0[0], bl0[1]);
            MMA_BF16(acc[1][0], ah[1], bl0[0], bl0[1]);
            MMA_BF16(acc[0][1], ah[0], bl0[2], bl0[3]);
            MMA_BF16(acc[1][1], ah[1], bl0[2], bl0[3]);
            MMA_BF16(acc[0][2], ah[0], bl1[0], bl1[1]);
            MMA_BF16(acc[1][2], ah[1], bl1[0], bl1[1]);
            MMA_BF16(acc[0][3], ah[0], bl1[2], bl1[3]);
            MMA_BF16(acc[1][3], ah[1], bl1[2], bl1[3]);
        }
        if (have && !APAIR) stsA(fn, p ^ 1);
        CPASYNC_WAIT0();
        __syncthreads();
        p ^= 1;
    }

    // ---------------- epilogue ----------------
    const int g  = lane >> 2;
    const int t4 = lane & 3;
#pragma unroll
    for (int mt = 0; mt < 2; ++mt)
#pragma unroll
        for (int h = 0; h < 2; ++h) {
            int row  = wr * 32 + mt * 16 + g + h * 8;
            int grow = row0 + row;
            const float* rp = (EPI == 2) ? res + (size_t)grow * D_ : nullptr;
            const float* pp = (EPI == 4) ? pe + (size_t)(grow & (N_ - 1)) * D_ : nullptr;
#pragma unroll
            for (int nt = 0; nt < 4; ++nt) {
                int cc = ch * 128 + wc * 32 + nt * 8 + t4 * 2;
                float v0 = acc[mt][nt][h*2]   + biasS[cc];
                float v1 = acc[mt][nt][h*2+1] + biasS[cc + 1];
                if (EPI == 1) { v0 = fmaxf(v0, 0.0f); v1 = fmaxf(v1, 0.0f); }
                if (EPI == 2) {
                    float2 rv = *(const float2*)&rp[cc];
                    v0 += rv.x; v1 += rv.y;
                }
                if (EPI == 4) {
                    float2 pv = *(const float2*)&pp[cc];
                    v0 += pv.x; v1 += pv.y;
                }
                v0 *= scale; v1 *= scale;
                if (oF) *(float2*)&oF[(size_t)grow * D_ + cc] = make_float2(v0, v1);
                if (oP) {
                    int pidx = cc >> 1;
                    oP[(size_t)grow * 256 + pidx]       = hi_pair(v0, v1);
                    oP[(size_t)grow * 256 + 128 + pidx] = lo_pair(v0, v1);
                }
            }
        }
}

// ---------------------------------------------------------------------------
// HMMA flash attention v4: double-buffered K/V. K via cp.async from pairs,
// V LDG-prefetched into registers during compute, converted+stored after PV.
// ---------------------------------------------------------------------------
#define AROWB   272
#define KVBUF   (64 * AROWB)              // 17408
#define AQ_OFF  0
#define AK_OFF  (128 * AROWB)
#define AV_OFF  (AK_OFF + 2 * KVBUF)
#define ASM_TOT (AV_OFF + 2 * KVBUF)      // 104448
#define QSCALE  0.1803368801111204f       // 0.125 * log2(e)

__global__ __launch_bounds__(256, 2) void attn_kernel(
    const uint32_t* __restrict__ qP,
    const uint32_t* __restrict__ kP,
    const float* __restrict__ v,
    uint32_t* __restrict__ ctxP)
{
    extern __shared__ __align__(16) char asm_[];
    const uint32_t smb = smem_u32(asm_);
    const int tid  = threadIdx.x;
    const int lane = tid & 31;
    const int warp = tid >> 5;
    const int bh   = blockIdx.y;
    const int b    = bh >> 2;
    const int h    = bh & 3;
    const int q0   = blockIdx.x * 128;
    const int g    = lane >> 2;
    const int t4   = lane & 3;

    // ---- stage Q from pairs
    {
        const int r  = tid >> 1;
        const int hf = tid & 1;
        const uint32_t* src = qP + (size_t)(b * N_ + q0 + r) * 256 + h * 32 + hf * 16;
        char* dh = asm_ + AQ_OFF + r * AROWB + hf * 64;
#pragma unroll
        for (int g2 = 0; g2 < 4; ++g2) {
            *(uint4*)(dh + g2 * 16)       = *(const uint4*)(src + g2 * 4);
            *(uint4*)(dh + 128 + g2 * 16) = *(const uint4*)(src + 128 + g2 * 4);
        }
    }

    // staging helpers
    const int kr  = tid >> 2;        // K stage row 0..63
    const int kqd = tid & 3;
    auto cpK = [&](int ti, int p) {
        const uint32_t* src = kP + (size_t)(b * N_ + ti * 64 + kr) * 256 + h * 32 + kqd * 8;
        uint32_t dst = smb + AK_OFF + p * KVBUF + kr * AROWB + kqd * 32;
        CPASYNC16(dst,            (const char*)src);
        CPASYNC16(dst + 16,       (const char*)(src + 4));
        CPASYNC16(dst + 128,      (const char*)(src + 128));
        CPASYNC16(dst + 128 + 16, (const char*)(src + 128 + 4));
    };
    auto ldgV = [&](int ti, float* f0, float* f1) {
        const float* v0p = v + ((size_t)(b * N_ + ti * 64 + 2*lane))     * D_ + h * HD_ + warp * 8;
        const float* v1p = v + ((size_t)(b * N_ + ti * 64 + 2*lane + 1)) * D_ + h * HD_ + warp * 8;
        *(float4*)&f0[0] = *(const float4*)&v0p[0];
        *(float4*)&f0[4] = *(const float4*)&v0p[4];
        *(float4*)&f1[0] = *(const float4*)&v1p[0];
        *(float4*)&f1[4] = *(const float4*)&v1p[4];
    };
    auto stV = [&](const float* f0, const float* f1, int p) {
#pragma unroll
        for (int j = 0; j < 8; ++j) {
            int hd = warp * 8 + j;
            char* base = asm_ + AV_OFF + p * KVBUF + hd * AROWB;
            *(uint32_t*)(base + lane * 4)       = hi_pair(f0[j], f1[j]);
            *(uint32_t*)(base + 128 + lane * 4) = lo_pair(f0[j], f1[j]);
        }
    };

    const uint32_t a_base = smb + AQ_OFF
        + (uint32_t)(warp * 16 + (lane & 15)) * AROWB + (uint32_t)(lane >> 4) * 16;
    const uint32_t kb_rel = AK_OFF
        + (uint32_t)(((lane >> 4) << 3) + (lane & 7)) * AROWB
        + (uint32_t)((lane >> 3) & 1) * 16;
    const uint32_t vb_rel = AV_OFF
        + (uint32_t)(((lane >> 4) << 3) + (lane & 7)) * AROWB
        + (uint32_t)((lane >> 3) & 1) * 16;

    float acc_o[8][4];
#pragma unroll
    for (int nt = 0; nt < 8; ++nt)
#pragma unroll
        for (int i = 0; i < 4; ++i) acc_o[nt][i] = 0.0f;
    float mrow[2] = {-1e30f, -1e30f};
    float lrow[2] = {0.0f, 0.0f};

    // ---- prologue: tile 0 into buffer 0
    {
        cpK(0, 0);
        CPASYNC_COMMIT();
        float f0[8], f1[8];
        ldgV(0, f0, f1);
        stV(f0, f1, 0);
        CPASYNC_WAIT0();
    }
    __syncthreads();

    int p = 0;
    for (int ti = 0; ti < 8; ++ti) {
        const bool have = (ti + 1 < 8);
        float nf0[8], nf1[8];
        if (have) {
            cpK(ti + 1, p ^ 1);
            CPASYNC_COMMIT();
            ldgV(ti + 1, nf0, nf1);
        }

        const uint32_t kb_base = smb + p * KVBUF + kb_rel;
        const uint32_t vb_base = smb + p * KVBUF + vb_rel;

        // ---- S = Q K^T
        float s[8][4];
#pragma unroll
        for (int nt = 0; nt < 8; ++nt)
#pragma unroll
            for (int i = 0; i < 4; ++i) s[nt][i] = 0.0f;
#pragma unroll
        for (int ks = 0; ks < 4; ++ks) {
            uint32_t ah[4], al[4];
            LDMX4(ah[0], ah[1], ah[2], ah[3], a_base + ks * 32);
            LDMX4(al[0], al[1], al[2], al[3], a_base + ks * 32 + 128);
#pragma unroll
            for (int npp = 0; npp < 2; ++npp) {
                const int np0 = npp * 2, np1 = npp * 2 + 1;
                uint32_t bh0[4], bl0[4], bh1[4], bl1[4];
                LDMX4(bh0[0], bh0[1], bh0[2], bh0[3],
                      kb_base + np0 * (16 * AROWB) + ks * 32);
                LDMX4(bl0[0], bl0[1], bl0[2], bl0[3],
                      kb_base + np0 * (16 * AROWB) + ks * 32 + 128);
                LDMX4(bh1[0], bh1[1], bh1[2], bh1[3],
                      kb_base + np1 * (16 * AROWB) + ks * 32);
                LDMX4(bl1[0], bl1[1], bl1[2], bl1[3],
                      kb_base + np1 * (16 * AROWB) + ks * 32 + 128);
                MMA_BF16(s[2*np0],     ah, bh0[0], bh0[1]);
                MMA_BF16(s[2*np0 + 1], ah, bh0[2], bh0[3]);
                MMA_BF16(s[2*np1],     ah, bh1[0], bh1[1]);
                MMA_BF16(s[2*np1 + 1], ah, bh1[2], bh1[3]);
                MMA_BF16(s[2*np0],     al, bh0[0], bh0[1]);
                MMA_BF16(s[2*np0 + 1], al, bh0[2], bh0[3]);
                MMA_BF16(s[2*np1],     al, bh1[0], bh1[1]);
                MMA_BF16(s[2*np1 + 1], al, bh1[2], bh1[3]);
                MMA_BF16(s[2*np0],     ah, bl0[0], bl0[1]);
                MMA_BF16(s[2*np0 + 1], ah, bl0[2], bl0[3]);
                MMA_BF16(s[2*np1],     ah, bl1[0], bl1[1]);
                MMA_BF16(s[2*np1 + 1], ah, bl1[2], bl1[3]);
            }
        }

        // ---- online softmax (base 2)
#pragma unroll
        for (int r2 = 0; r2 < 2; ++r2) {
            float mx = -1e30f;
#pragma unroll
            for (int nt = 0; nt < 8; ++nt)
                mx = fmaxf(mx, fmaxf(s[nt][r2*2], s[nt][r2*2+1]));
#pragma unroll
            for (int off = 1; off <= 2; off <<= 1)
                mx = fmaxf(mx, __shfl_xor_sync(0xffffffffu, mx, off));
            float mnew = fmaxf(mrow[r2], mx);
            float corr = fexp2(mrow[r2] - mnew);
            float ps = 0.0f;
#pragma unroll
            for (int nt = 0; nt < 8; ++nt) {
                float p0 = fexp2(s[nt][r2*2]   - mnew);
                float p1 = fexp2(s[nt][r2*2+1] - mnew);
                s[nt][r2*2] = p0; s[nt][r2*2+1] = p1;
                ps += p0 + p1;
            }
#pragma unroll
            for (int off = 1; off <= 2; off <<= 1)
                ps += __shfl_xor_sync(0xffffffffu, ps, off);
            lrow[r2] = lrow[r2] * corr + ps;
            mrow[r2] = mnew;
#pragma unroll
            for (int nt = 0; nt < 8; ++nt) {
                acc_o[nt][r2*2]   *= corr;
                acc_o[nt][r2*2+1] *= corr;
            }
        }

        // ---- O += P V
#pragma unroll
        for (int kt = 0; kt < 4; ++kt) {
            uint32_t pah[4], pal[4];
            pah[0] = hi_pair(s[2*kt][0],   s[2*kt][1]);
            pah[1] = hi_pair(s[2*kt][2],   s[2*kt][3]);
            pah[2] = hi_pair(s[2*kt+1][0], s[2*kt+1][1]);
            pah[3] = hi_pair(s[2*kt+1][2], s[2*kt+1][3]);
            pal[0] = lo_pair(s[2*kt][0],   s[2*kt][1]);
            pal[1] = lo_pair(s[2*kt][2],   s[2*kt][3]);
            pal[2] = lo_pair(s[2*kt+1][0], s[2*kt+1][1]);
            pal[3] = lo_pair(s[2*kt+1][2], s[2*kt+1][3]);
#pragma unroll
            for (int npp = 0; npp < 2; ++npp) {
                const int np0 = npp * 2, np1 = npp * 2 + 1;
                uint32_t vh0[4], vl0[4], vh1[4], vl1[4];
                LDMX4(vh0[0], vh0[1], vh0[2], vh0[3],
                      vb_base + np0 * (16 * AROWB) + kt * 32);
                LDMX4(vl0[0], vl0[1], vl0[2], vl0[3],
                      vb_base + np0 * (16 * AROWB) + kt * 32 + 128);
                LDMX4(vh1[0], vh1[1], vh1[2], vh1[3],
                      vb_base + np1 * (16 * AROWB) + kt * 32);
                LDMX4(vl1[0], vl1[1], vl1[2], vl1[3],
                      vb_base + np1 * (16 * AROWB) + kt * 32 + 128);
                MMA_BF16(acc_o[2*np0],     pah, vh0[0], vh0[1]);
                MMA_BF16(acc_o[2*np0 + 1], pah, vh0[2], vh0[3]);
                MMA_BF16(acc_o[2*np1],     pah, vh1[0], vh1[1]);
                MMA_BF16(acc_o[2*np1 + 1], pah, vh1[2], vh1[3]);
                MMA_BF16(acc_o[2*np0],     pal, vh0[0], vh0[1]);
                MMA_BF16(acc_o[2*np0 + 1], pal, vh0[2], vh0[3]);
                MMA_BF16(acc_o[2*np1],     pal, vh1[0], vh1[1]);
                MMA_BF16(acc_o[2*np1 + 1], pal, vh1[2], vh1[3]);
                MMA_BF16(acc_o[2*np0],     pah, vl0[0], vl0[1]);
                MMA_BF16(acc_o[2*np0 + 1], pah, vl0[2], vl0[3]);
                MMA_BF16(acc_o[2*np1],     pah, vl1[0], vl1[1]);
                MMA_BF16(acc_o[2*np1 + 1], pah, vl1[2], vl1[3]);
            }
        }

        if (have) stV(nf0, nf1, p ^ 1);
        CPASYNC_WAIT0();
        __syncthreads();
        p ^= 1;
    }

    // ---- write ctx as pair-plane
    float inv0 = 1.0f / lrow[0];
    float inv1 = 1.0f / lrow[1];
#pragma unroll
    for (int r2 = 0; r2 < 2; ++r2) {
        int grow = b * N_ + q0 + warp * 16 + g + r2 * 8;
        float inv = r2 ? inv1 : inv0;
#pragma unroll
        for (int nt = 0; nt < 8; ++nt) {
            float v0 = acc_o[nt][r2*2]   * inv;
            float v1 = acc_o[nt][r2*2+1] * inv;
            int pidx = h * 32 + nt * 4 + t4;
            ctxP[(size_t)grow * 256 + pidx]       = hi_pair(v0, v1);
            ctxP[(size_t)grow * 256 + 128 + pidx] = lo_pair(v0, v1);
        }
    }
}

// ---------------------------------------------------------------------------
// mean-pool + classifier
// ---------------------------------------------------------------------------
__global__ __launch_bounds__(256) void pool_cls_kernel(
    const float* __restrict__ xm,
    const float* __restrict__ Wc,
    const float* __restrict__ bc,
    float* __restrict__ out)
{
    __shared__ float pooled[D_];
    const int b = blockIdx.x;
    const int t = threadIdx.x;
    float s = 0.0f;
    const float* p = xm + (size_t)b * N_ * D_ + t;
#pragma unroll 8
    for (int n = 0; n < N_; ++n) s += p[(size_t)n * D_];
    pooled[t] = s * (1.0f / (float)N_);
    __syncthreads();
    if (t < 2) {
        float a = bc[t];
        for (int c = 0; c < D_; ++c) a = fmaf(pooled[c], Wc[t * D_ + c], a);
        out[b * 2 + t] = a;
    }
}

// ---------------------------------------------------------------------------
// Launch
// ---------------------------------------------------------------------------
static void* symp(const void* s) {
    void* p = nullptr;
    cudaGetSymbolAddress(&p, s);
    return p;
}

extern "C" void kernel_launch(void* const* d_in, const int* in_sizes, int n_in,
                              void* d_out, int out_size)
{
    const float* x   = (const float*)d_in[0];
    const float* y   = (const float*)d_in[1];
    const float* Wr  = (const float*)d_in[3];
    const float* br  = (const float*)d_in[4];
    const float* Wf  = (const float*)d_in[5];
    const float* bf  = (const float*)d_in[6];
    const float* g_x = (const float*)d_in[7];
    const float* b_x = (const float*)d_in[8];
    const float* g_y = (const float*)d_in[9];
    const float* b_y = (const float*)d_in[10];
    const float* Wq  = (const float*)d_in[11];
    const float* bq  = (const float*)d_in[12];
    const float* Wk  = (const float*)d_in[13];
    const float* bk  = (const float*)d_in[14];
    const float* Wv  = (const float*)d_in[15];
    const float* bv  = (const float*)d_in[16];
    const float* Wo  = (const float*)d_in[17];
    const float* bo  = (const float*)d_in[18];
    const float* g_m = (const float*)d_in[19];
    const float* b_m = (const float*)d_in[20];
    const float* W1  = (const float*)d_in[21];
    const float* b1  = (const float*)d_in[22];
    const float* W2  = (const float*)d_in[23];
    const float* b2  = (const float*)d_in[24];
    const float* Wc  = (const float*)d_in[25];
    const float* bc  = (const float*)d_in[26];
    float* out = (float*)d_out;

    float*    xp   = (float*)symp(g_xp);
    float*    yp   = (float*)symp(g_yp);
    float*    vb_  = (float*)symp(g_v);
    float*    xres = (float*)symp(g_xres);
    float*    xmlp = (float*)symp(g_xmlp);
    float*    pe   = (float*)symp(g_pe);
    uint32_t* xpP  = (uint32_t*)symp(g_xpP);
    uint32_t* ypP  = (uint32_t*)symp(g_ypP);
    uint32_t* qP   = (uint32_t*)symp(g_qP);
    uint32_t* kP   = (uint32_t*)symp(g_kP);
    uint32_t* ctxP = (uint32_t*)symp(g_ctxP);
    uint32_t* xrsP = (uint32_t*)symp(g_xrsP);
    uint32_t* hidP = (uint32_t*)symp(g_hidP);
    uint32_t* wb   = (uint32_t*)symp(g_wbuf);

    static bool attr_set = false;
    if (!attr_set) {
        cudaFuncSetAttribute(attn_kernel,
                             cudaFuncAttributeMaxDynamicSharedMemorySize, ASM_TOT);
        cudaFuncSetAttribute(hmma_gemm_n128<0, 1>,
                             cudaFuncAttributeMaxDynamicSharedMemorySize, SM_TOT_S);
        cudaFuncSetAttribute(hmma_gemm_n128<1, 1>,
                             cudaFuncAttributeMaxDynamicSharedMemorySize, SM_TOT_S);
        cudaFuncSetAttribute(hmma_gemm_n128<2, 1>,
                             cudaFuncAttributeMaxDynamicSharedMemorySize, SM_TOT_S);
        cudaFuncSetAttribute(hmma_gemm_n128<4, 0>,
                             cudaFuncAttributeMaxDynamicSharedMemorySize, SM_TOT_S);
        attr_set = true;
    }

    dim3 gs(M_ / 64 * 2);  // 1024 CTAs
    dim3 bb(256);
    dim3 lg(M_ / 8);       // 4096 CTAs (LN)

    prep_kernel<<<(WB_TOT + N_ * D_ + 255) / 256, 256>>>(Wr, Wf, Wq, Wk, Wv, Wo, W1, W2);

    // xp = x @ Wr^T + br + pe ; LN in place + pairs
    hmma_gemm_n128<4, 0><<<gs, bb, SM_TOT_S>>>(x, nullptr, 769, 25, wb + WR_OFF, 800, 0,
        br, nullptr, nullptr, pe, 1.0f, xp, nullptr, nullptr, nullptr);
    ln_kernel<<<lg, bb>>>(xp, g_x, b_x, 1, xpP);
    // yp = y @ Wf^T + bf + pe ; LN -> pairs only
    hmma_gemm_n128<4, 0><<<gs, bb, SM_TOT_S>>>(y, nullptr, 674, 22, wb + WF_OFF, 704, 0,
        bf, nullptr, nullptr, pe, 1.0f, yp, nullptr, nullptr, nullptr);
    ln_kernel<<<lg, bb>>>(yp, g_y, b_y, 0, ypP);
    // q (scaled pairs)
    hmma_gemm_n128<0, 1><<<gs, bb, SM_TOT_S>>>(nullptr, xpP, 256, 8, wb + WQ_OFF, 256, 0,
        bq, nullptr, nullptr, nullptr, QSCALE, nullptr, nullptr, qP, nullptr);
    // k (pairs) + v (fp32) fused
    hmma_gemm_n128<0, 1><<<dim3(M_ / 64 * 2, 2), bb, SM_TOT_S>>>(nullptr, ypP, 256, 8,
        wb + WK_OFF, 256, 256 * 256,
        bk, bv, nullptr, nullptr, 1.0f, nullptr, vb_, kP, nullptr);
    // attention (double-buffered)
    dim3 ag(N_ / 128, B_ * H_);
    attn_kernel<<<ag, bb, ASM_TOT>>>(qP, kP, vb_, ctxP);
    // xres = xp + ctx @ Wo^T + bo ; LN in place + pairs
    hmma_gemm_n128<2, 1><<<gs, bb, SM_TOT_S>>>(nullptr, ctxP, 256, 8, wb + WO_OFF, 256, 0,
        bo, nullptr, xp, nullptr, 1.0f, xres, nullptr, nullptr, nullptr);
    ln_kernel<<<lg, bb>>>(xres, g_m, b_m, 1, xrsP);
    // hid = relu(xres @ W1^T + b1) -> pairs only
    hmma_gemm_n128<1, 1><<<gs, bb, SM_TOT_S>>>(nullptr, xrsP, 256, 8, wb + W1_OFF, 256, 0,
        b1, nullptr, nullptr, nullptr, 1.0f, nullptr, nullptr, hidP, nullptr);
    // xmlp = xres + hid @ W2^T + b2
    hmma_gemm_n128<2, 1><<<gs, bb, SM_TOT_S>>>(nullptr, hidP, 256, 8, wb + W2_OFF, 256, 0,
        b2, nullptr, xres, nullptr, 1.0f, xmlp, nullptr, nullptr, nullptr);
    // pool + classifier
    pool_cls_kernel<<<B_, bb>>>(xmlp, Wc, bc, out);
}

// round 16
// speedup vs baseline: 1.7447x; 1.7447x over previous
#include <cuda_runtime.h>
#include <cuda_bf16.h>
#include <math.h>
#include <stdint.h>

// ---------------------------------------------------------------------------
// Model dims
// ---------------------------------------------------------------------------
#define B_      64
#define N_      512
#define D_      256
#define H_      4
#define HD_     64
#define M_      (B_ * N_)         // 32768 rows
#define EPS_    1e-5f

// ---------------------------------------------------------------------------
// Scratch: fp32 staging + pair-plane (hi 128 words | lo 128 words per row)
// ---------------------------------------------------------------------------
__device__ float    g_xp  [M_ * D_];
__device__ float    g_yp  [M_ * D_];
__device__ float    g_v   [M_ * D_];
__device__ float    g_xres[M_ * D_];
__device__ float    g_xmlp[M_ * D_];
__device__ float    g_pe  [N_ * D_];
__device__ uint32_t g_xpP [M_ * D_];
__device__ uint32_t g_ypP [M_ * D_];
__device__ uint32_t g_qP  [M_ * D_];
__device__ uint32_t g_kP  [M_ * D_];
__device__ uint32_t g_ctxP[M_ * D_];
__device__ uint32_t g_xrsP[M_ * D_];
__device__ uint32_t g_hidP[M_ * D_];

// bf16 hi/lo weight scratch (chunk-interleaved: 16 hi words, 16 lo words / 32k)
#define WR_OFF  0
#define WF_OFF  (WR_OFF + 256 * 800)
#define WQ_OFF  (WF_OFF + 256 * 704)
#define WK_OFF  (WQ_OFF + 256 * 256)
#define WV_OFF  (WK_OFF + 256 * 256)
#define WO_OFF  (WV_OFF + 256 * 256)
#define W1_OFF  (WO_OFF + 256 * 256)
#define W2_OFF  (W1_OFF + 256 * 256)
#define WB_TOT  (W2_OFF + 256 * 256)
__device__ uint32_t g_wbuf[WB_TOT];

// ---------------------------------------------------------------------------
__device__ __forceinline__ uint32_t hi_pair(float x0, float x1) {
    uint32_t a = __float_as_uint(x0), b = __float_as_uint(x1);
    return (b & 0xffff0000u) | (a >> 16);
}
__device__ __forceinline__ uint32_t lo_pair(float x0, float x1) {
    float l0 = x0 - __uint_as_float(__float_as_uint(x0) & 0xffff0000u);
    float l1 = x1 - __uint_as_float(__float_as_uint(x1) & 0xffff0000u);
    uint32_t a = (uint32_t)__bfloat16_as_ushort(__float2bfloat16(l0));
    uint32_t b = (uint32_t)__bfloat16_as_ushort(__float2bfloat16(l1));
    return (b << 16) | a;
}

__device__ __forceinline__ uint32_t smem_u32(const void* p) {
    uint32_t a;
    asm("{ .reg .u64 t; cvta.to.shared.u64 t, %1; cvt.u32.u64 %0, t; }"
        : "=r"(a) : "l"(p));
    return a;
}

#define LDMX4(r0, r1, r2, r3, addr) \
    asm volatile("ldmatrix.sync.aligned.m8n8.x4.shared.b16 {%0,%1,%2,%3}, [%4];" \
                 : "=r"(r0), "=r"(r1), "=r"(r2), "=r"(r3) : "r"(addr))

#define MMA_BF16(c, a, b0, b1) \
    asm volatile("mma.sync.aligned.m16n8k16.row.col.f32.bf16.bf16.f32 " \
                 "{%0,%1,%2,%3}, {%4,%5,%6,%7}, {%8,%9}, {%0,%1,%2,%3};" \
                 : "+f"((c)[0]), "+f"((c)[1]), "+f"((c)[2]), "+f"((c)[3]) \
                 : "r"((a)[0]), "r"((a)[1]), "r"((a)[2]), "r"((a)[3]), \
                   "r"(b0), "r"(b1))

#define CPASYNC16(dst, src) \
    asm volatile("cp.async.cg.shared.global [%0], [%1], 16;" \
                 :: "r"(dst), "l"(src))
#define CPASYNC_COMMIT()  asm volatile("cp.async.commit_group;" ::: "memory")
#define CPASYNC_WAIT0()   asm volatile("cp.async.wait_group 0;" ::: "memory")

// fast 2^x for x <= 0; rel err ~1.5e-5; no MUFU
__device__ __forceinline__ float fexp2(float x) {
    x = fmaxf(x, -80.0f);
    float n = floorf(x);
    float f = x - n;
    float p = 1.5404e-4f;
    p = fmaf(p, f, 1.333356e-3f);
    p = fmaf(p, f, 9.618130e-3f);
    p = fmaf(p, f, 5.550411e-2f);
    p = fmaf(p, f, 2.402265e-1f);
    p = fmaf(p, f, 6.931472e-1f);
    p = fmaf(p, f, 1.0f);
    return __int_as_float(__float_as_int(p) + ((int)n << 23));
}

// ---------------------------------------------------------------------------
// Prologue: weight hi/lo conversion + PE table
// ---------------------------------------------------------------------------
__global__ void prep_kernel(const float* __restrict__ Wr, const float* __restrict__ Wf,
                            const float* __restrict__ Wq, const float* __restrict__ Wk,
                            const float* __restrict__ Wv, const float* __restrict__ Wo,
                            const float* __restrict__ W1, const float* __restrict__ W2) {
    int idx = blockIdx.x * blockDim.x + threadIdx.x;
    if (idx < WB_TOT) {
        const float* W; int K, rowU32, base;
        if      (idx < WF_OFF) { W = Wr; K = 769; rowU32 = 800; base = WR_OFF; }
        else if (idx < WQ_OFF) { W = Wf; K = 674; rowU32 = 704; base = WF_OFF; }
        else if (idx < WK_OFF) { W = Wq; K = 256; rowU32 = 256; base = WQ_OFF; }
        else if (idx < WV_OFF) { W = Wk; K = 256; rowU32 = 256; base = WK_OFF; }
        else if (idx < WO_OFF) { W = Wv; K = 256; rowU32 = 256; base = WV_OFF; }
        else if (idx < W1_OFF) { W = Wo; K = 256; rowU32 = 256; base = WO_OFF; }
        else if (idx < W2_OFF) { W = W1; K = 256; rowU32 = 256; base = W1_OFF; }
        else                   { W = W2; K = 256; rowU32 = 256; base = W2_OFF; }
        int j   = idx - base;
        int row = j / rowU32;
        int jj  = j - row * rowU32;
        int c   = jj >> 5;
        int t   = jj & 31;
        int e0  = c * 32 + ((t & 15) << 1);
        float v0 = (e0     < K) ? W[(size_t)row * K + e0]     : 0.0f;
        float v1 = (e0 + 1 < K) ? W[(size_t)row * K + e0 + 1] : 0.0f;
        g_wbuf[idx] = (t < 16) ? hi_pair(v0, v1) : lo_pair(v0, v1);
    } else if (idx < WB_TOT + N_ * D_) {
        int j   = idx - WB_TOT;
        int pos = j >> 8;
        int c   = j & 255;
        int i2  = c & ~1;
        float div = expf(-logf(10000.0f) * (float)i2 / (float)D_);
        float ang = (float)pos * div;
        g_pe[j] = (c & 1) ? cosf(ang) : sinf(ang);
    }
}

// ---------------------------------------------------------------------------
// Row LayerNorm: warp per 256-col row. Optional fp32 write-back + pair output.
// ---------------------------------------------------------------------------
__global__ __launch_bounds__(256) void ln_kernel(
    float* __restrict__ io,
    const float* __restrict__ gamma,
    const float* __restrict__ beta,
    int writeF,
    uint32_t* __restrict__ outP)
{
    const int row  = blockIdx.x * 8 + (threadIdx.x >> 5);
    const int lane = threadIdx.x & 31;
    float* p = io + (size_t)row * D_ + lane * 8;
    float4 a = *(float4*)p;
    float4 b = *(float4*)(p + 4);
    float s = a.x + a.y + a.z + a.w + b.x + b.y + b.z + b.w;
    float q = a.x*a.x + a.y*a.y + a.z*a.z + a.w*a.w
            + b.x*b.x + b.y*b.y + b.z*b.z + b.w*b.w;
#pragma unroll
    for (int off = 16; off > 0; off >>= 1) {
        s += __shfl_xor_sync(0xffffffffu, s, off);
        q += __shfl_xor_sync(0xffffffffu, q, off);
    }
    float mu  = s * (1.0f / 256.0f);
    float var = q * (1.0f / 256.0f) - mu * mu;
    float rs  = rsqrtf(var + EPS_);
    const float* gp = gamma + lane * 8;
    const float* bp = beta  + lane * 8;
    float4 g0 = *(const float4*)gp,  g1 = *(const float4*)(gp + 4);
    float4 b0 = *(const float4*)bp,  b1 = *(const float4*)(bp + 4);
    a.x = (a.x - mu) * rs * g0.x + b0.x;  a.y = (a.y - mu) * rs * g0.y + b0.y;
    a.z = (a.z - mu) * rs * g0.z + b0.z;  a.w = (a.w - mu) * rs * g0.w + b0.w;
    b.x = (b.x - mu) * rs * g1.x + b1.x;  b.y = (b.y - mu) * rs * g1.y + b1.y;
    b.z = (b.z - mu) * rs * g1.z + b1.z;  b.w = (b.w - mu) * rs * g1.w + b1.w;
    if (writeF) {
        *(float4*)p       = a;
        *(float4*)(p + 4) = b;
    }
    uint4 hw = make_uint4(hi_pair(a.x, a.y), hi_pair(a.z, a.w),
                          hi_pair(b.x, b.y), hi_pair(b.z, b.w));
    uint4 lw = make_uint4(lo_pair(a.x, a.y), lo_pair(a.z, a.w),
                          lo_pair(b.x, b.y), lo_pair(b.z, b.w));
    *(uint4*)(outP + (size_t)row * 256 + lane * 4)       = hw;
    *(uint4*)(outP + (size_t)row * 256 + 128 + lane * 4) = lw;
}

// ---------------------------------------------------------------------------
// hmma_gemm_n128: 64x128 tile, 3 CTAs/SM, warp tile 32x32, generalized K.
// APAIR=1: A staged via cp.async from pair-plane buffer. gridDim.y picks set.
// EPI: 0=+bias 1=relu(+bias) 2=+bias+res 4=+bias+pe
// ---------------------------------------------------------------------------
#define ROWB     144
#define ABUF_S   (64 * ROWB)
#define BBUF_S   (128 * ROWB)
#define BUFSZ_S  (ABUF_S + BBUF_S)
#define SM_TOT_S (2 * BUFSZ_S)

template <int EPI, int APAIR>
__global__ __launch_bounds__(256, 3) void hmma_gemm_n128(
    const float* __restrict__ A, const uint32_t* __restrict__ Ap,
    int K, int NC,
    const uint32_t* __restrict__ Wbf, int rowU32, int wstride,
    const float* __restrict__ bias, const float* __restrict__ bias2,
    const float* __restrict__ res,
    const float* __restrict__ pe, float scale,
    float* __restrict__ outF, float* __restrict__ outF2,
    uint32_t* __restrict__ outP, uint32_t* __restrict__ outP2)
{
    extern __shared__ __align__(16) char sm[];
    const uint32_t smb = smem_u32(sm);
    const int tid  = threadIdx.x;
    const int lane = tid & 31;
    const int warp = tid >> 5;
    const int wr   = warp >> 2;
    const int wc   = warp & 3;
    const int ch   = blockIdx.x & 1;
    const int row0 = (blockIdx.x >> 1) * 64;

    const float* biasS = blockIdx.y ? bias2 : bias;
    float*       oF    = blockIdx.y ? outF2 : outF;
    uint32_t*    oP    = blockIdx.y ? outP2 : outP;

    const int arow = tid >> 2;
    const int aq   = tid & 3;
    const float*    Apf = A  ? A  + (size_t)(row0 + arow) * K + aq * 8 : nullptr;
    const uint32_t* App = Ap ? Ap + (size_t)(row0 + arow) * K : nullptr;
    const int brow = tid >> 1;
    const int bhf  = tid & 1;
    const uint32_t* Wp = Wbf + (size_t)blockIdx.y * wstride
                       + (size_t)(ch * 128 + brow) * rowU32;

    float acc[2][4][4];
#pragma unroll
    for (int mt = 0; mt < 2; ++mt)
#pragma unroll
        for (int nt = 0; nt < 4; ++nt)
#pragma unroll
            for (int i = 0; i < 4; ++i) acc[mt][nt][i] = 0.0f;

    const uint32_t a_rel = (uint32_t)(wr * 32 + (lane & 15)) * ROWB
                         + (uint32_t)(lane >> 4) * 16;
    const uint32_t b_rel = ABUF_S
                         + (uint32_t)(wc * 32 + ((lane >> 4) << 3) + (lane & 7)) * ROWB
                         + (uint32_t)((lane >> 3) & 1) * 16;

    auto ldgA = [&](int c, float* f) {
#pragma unroll
        for (int j = 0; j < 8; ++j) {
            int kg = c * 32 + aq * 8 + j;
            f[j] = (kg < K) ? Apf[c * 32 + j] : 0.0f;
        }
    };
    auto stsA = [&](const float* f, int p) {
        uint32_t hw[4], lw[4];
#pragma unroll
        for (int w = 0; w < 4; ++w) {
            hw[w] = hi_pair(f[2*w], f[2*w+1]);
            lw[w] = lo_pair(f[2*w], f[2*w+1]);
        }
        char* dh = sm + p * BUFSZ_S + arow * ROWB + aq * 16;
        *(uint4*)dh        = make_uint4(hw[0], hw[1], hw[2], hw[3]);
        *(uint4*)(dh + 64) = make_uint4(lw[0], lw[1], lw[2], lw[3]);
    };
    auto cpA = [&](int c, int p) {
        uint32_t dst = smb + p * BUFSZ_S + arow * ROWB + aq * 16;
        const char* srcH = (const char*)(App + c * 16 + aq * 4);
        const char* srcL = (const char*)(App + (K >> 1) + c * 16 + aq * 4);
        CPASYNC16(dst, srcH);
        CPASYNC16(dst + 64, srcL);
    };
    auto cpB = [&](int c, int p) {
        uint32_t dst = smb + p * BUFSZ_S + ABUF_S + brow * ROWB + bhf * 64;
        const char* src = (const char*)(Wp + c * 32 + bhf * 16);
#pragma unroll
        for (int g2 = 0; g2 < 4; ++g2)
            CPASYNC16(dst + g2 * 16, src + g2 * 16);
    };

    if (APAIR) {
        cpA(0, 0); cpB(0, 0);
        CPASYNC_COMMIT();
        CPASYNC_WAIT0();
    } else {
        float f0[8];
        ldgA(0, f0);
        cpB(0, 0);
        CPASYNC_COMMIT();
        stsA(f0, 0);
        CPASYNC_WAIT0();
    }
    __syncthreads();

    int p = 0;
    for (int c = 0; c < NC; ++c) {
        const bool have = (c + 1 < NC);
        float fn[8];
        if (have) {
            if (APAIR) { cpA(c + 1, p ^ 1); cpB(c + 1, p ^ 1); CPASYNC_COMMIT(); }
            else       { cpB(c + 1, p ^ 1); CPASYNC_COMMIT(); ldgA(c + 1, fn); }
        }
        const uint32_t ab = smb + p * BUFSZ_S + a_rel;
        const uint32_t bb = smb + p * BUFSZ_S + b_rel;
#pragma unroll
        for (int ks = 0; ks < 2; ++ks) {
            uint32_t ah[2][4], al[2][4];
#pragma unroll
            for (int mt = 0; mt < 2; ++mt) {
                LDMX4(ah[mt][0], ah[mt][1], ah[mt][2], ah[mt][3],
                      ab + mt * (16 * ROWB) + ks * 32);
                LDMX4(al[mt][0], al[mt][1], al[mt][2], al[mt][3],
                      ab + mt * (16 * ROWB) + ks * 32 + 64);
            }
            uint32_t bh0[4], bl0[4], bh1[4], bl1[4];
            LDMX4(bh0[0], bh0[1], bh0[2], bh0[3], bb + ks * 32);
            LDMX4(bl0[0], bl0[1], bl0[2], bl0[3], bb + ks * 32 + 64);
            LDMX4(bh1[0], bh1[1], bh1[2], bh1[3], bb + 16 * ROWB + ks * 32);
            LDMX4(bl1[0], bl1[1], bl1[2], bl1[3], bb + 16 * ROWB + ks * 32 + 64);
            // term 1
            MMA_BF16(acc[0][0], ah[0], bh0[0], bh0[1]);
            MMA_BF16(acc[1][0], ah[1], bh0[0], bh0[1]);
            MMA_BF16(acc[0][1], ah[0], bh0[2], bh0[3]);
            MMA_BF16(acc[1][1], ah[1], bh0[2], bh0[3]);
            MMA_BF16(acc[0][2], ah[0], bh1[0], bh1[1]);
            MMA_BF16(acc[1][2], ah[1], bh1[0], bh1[1]);
            MMA_BF16(acc[0][3], ah[0], bh1[2], bh1[3]);
            MMA_BF16(acc[1][3], ah[1], bh1[2], bh1[3]);
            // term 2
            MMA_BF16(acc[0][0], al[0], bh0[0], bh0[1]);
            MMA_BF16(acc[1][0], al[1], bh0[0], bh0[1]);
            MMA_BF16(acc[0][1], al[0], bh0[2], bh0[3]);
            MMA_BF16(acc[1][1], al[1], bh0[2], bh0[3]);
            MMA_BF16(acc[0][2], al[0], bh1[0], bh1[1]);
            MMA_BF16(acc[1][2], al[1], bh1[0], bh1[1]);
            MMA_BF16(acc[0][3], al[0], bh1[2], bh1[3]);
            MMA_BF16(acc[1][3], al[1], bh1[2], bh1[3]);
            // term 3
            MMA_BF16(acc[0][0], ah[0], bl0[0], bl0[1]);
            MMA_BF16(acc[1][0], ah[1], bl0[0], bl0[1]);
            MMA_BF16(acc[0][1], ah[0], bl0[2], bl0[3]);
            MMA_BF16(acc[1][1], ah[1], bl0[2], bl0[3]);
            MMA_BF16(acc[0][2], ah[0], bl1[0], bl1[1]);
            MMA_BF16(acc[1][2], ah[1], bl1[0], bl1[1]);
            MMA_BF16(acc[0][3], ah[0], bl1[2], bl1[3]);
            MMA_BF16(acc[1][3], ah[1], bl1[2], bl1[3]);
        }
        if (have && !APAIR) stsA(fn, p ^ 1);
        CPASYNC_WAIT0();
        __syncthreads();
        p ^= 1;
    }

    // ---------------- epilogue ----------------
    const int g  = lane >> 2;
    const int t4 = lane & 3;
#pragma unroll
    for (int mt = 0; mt < 2; ++mt)
#pragma unroll
        for (int h = 0; h < 2; ++h) {
            int row  = wr * 32 + mt * 16 + g + h * 8;
            int grow = row0 + row;
            const float* rp = (EPI == 2) ? res + (size_t)grow * D_ : nullptr;
            const float* pp = (EPI == 4) ? pe + (size_t)(grow & (N_ - 1)) * D_ : nullptr;
#pragma unroll
            for (int nt = 0; nt < 4; ++nt) {
                int cc = ch * 128 + wc * 32 + nt * 8 + t4 * 2;
                float v0 = acc[mt][nt][h*2]   + biasS[cc];
                float v1 = acc[mt][nt][h*2+1] + biasS[cc + 1];
                if (EPI == 1) { v0 = fmaxf(v0, 0.0f); v1 = fmaxf(v1, 0.0f); }
                if (EPI == 2) {
                    float2 rv = *(const float2*)&rp[cc];
                    v0 += rv.x; v1 += rv.y;
                }
                if (EPI == 4) {
                    float2 pv = *(const float2*)&pp[cc];
                    v0 += pv.x; v1 += pv.y;
                }
                v0 *= scale; v1 *= scale;
                if (oF) *(float2*)&oF[(size_t)grow * D_ + cc] = make_float2(v0, v1);
                if (oP) {
                    int pidx = cc >> 1;
                    oP[(size_t)grow * 256 + pidx]       = hi_pair(v0, v1);
                    oP[(size_t)grow * 256 + 128 + pidx] = lo_pair(v0, v1);
                }
            }
        }
}

// ---------------------------------------------------------------------------
// HMMA flash attention v5: R14 structure (single V buffer, serial V stage)
// + double-buffered K only (next-tile cp.async issued after this tile's wait,
// overlapped with the 288 MMAs). Register budget identical to R14.
// ---------------------------------------------------------------------------
#define AROWB   272
#define KBUF    (64 * AROWB)
#define AQ_OFF  0
#define AK_OFF  (128 * AROWB)
#define AV_OFF  (AK_OFF + 2 * KBUF)
#define ASM_TOT (AV_OFF + 64 * AROWB)     // 87040
#define QSCALE  0.1803368801111204f       // 0.125 * log2(e)

__global__ __launch_bounds__(256, 2) void attn_kernel(
    const uint32_t* __restrict__ qP,
    const uint32_t* __restrict__ kP,
    const float* __restrict__ v,
    uint32_t* __restrict__ ctxP)
{
    extern __shared__ __align__(16) char asm_[];
    const uint32_t smb = smem_u32(asm_);
    const int tid  = threadIdx.x;
    const int lane = tid & 31;
    const int warp = tid >> 5;
    const int bh   = blockIdx.y;
    const int b    = bh >> 2;
    const int h    = bh & 3;
    const int q0   = blockIdx.x * 128;
    const int g    = lane >> 2;
    const int t4   = lane & 3;

    // ---- stage Q from pairs
    {
        const int r  = tid >> 1;
        const int hf = tid & 1;
        const uint32_t* src = qP + (size_t)(b * N_ + q0 + r) * 256 + h * 32 + hf * 16;
        char* dh = asm_ + AQ_OFF + r * AROWB + hf * 64;
#pragma unroll
        for (int g2 = 0; g2 < 4; ++g2) {
            *(uint4*)(dh + g2 * 16)       = *(const uint4*)(src + g2 * 4);
            *(uint4*)(dh + 128 + g2 * 16) = *(const uint4*)(src + 128 + g2 * 4);
        }
    }

    const int kr  = tid >> 2;
    const int kqd = tid & 3;
    auto cpK = [&](int ti, int p) {
        const uint32_t* src = kP + (size_t)(b * N_ + ti * 64 + kr) * 256 + h * 32 + kqd * 8;
        uint32_t dst = smb + AK_OFF + p * KBUF + kr * AROWB + kqd * 32;
        CPASYNC16(dst,            (const char*)src);
        CPASYNC16(dst + 16,       (const char*)(src + 4));
        CPASYNC16(dst + 128,      (const char*)(src + 128));
        CPASYNC16(dst + 128 + 16, (const char*)(src + 128 + 4));
    };

    const uint32_t a_base = smb + AQ_OFF
        + (uint32_t)(warp * 16 + (lane & 15)) * AROWB + (uint32_t)(lane >> 4) * 16;
    const uint32_t kb_rel = AK_OFF
        + (uint32_t)(((lane >> 4) << 3) + (lane & 7)) * AROWB
        + (uint32_t)((lane >> 3) & 1) * 16;
    const uint32_t vb_base = smb + AV_OFF
        + (uint32_t)(((lane >> 4) << 3) + (lane & 7)) * AROWB
        + (uint32_t)((lane >> 3) & 1) * 16;

    float acc_o[8][4];
#pragma unroll
    for (int nt = 0; nt < 8; ++nt)
#pragma unroll
        for (int i = 0; i < 4; ++i) acc_o[nt][i] = 0.0f;
    float mrow[2] = {-1e30f, -1e30f};
    float lrow[2] = {0.0f, 0.0f};

    // ---- prologue: K(0) in flight
    cpK(0, 0);
    CPASYNC_COMMIT();

    int p = 0;
    for (int ti = 0; ti < 8; ++ti) {
        const bool have = (ti + 1 < 8);
        // ---- stage V(ti) serially (R14 path; prev PV readers done via sync below)
        __syncthreads();
        {
            const float* v0p = v + ((size_t)(b * N_ + ti * 64 + 2*lane))     * D_ + h * HD_ + warp * 8;
            const float* v1p = v + ((size_t)(b * N_ + ti * 64 + 2*lane + 1)) * D_ + h * HD_ + warp * 8;
            float f0[8], f1[8];
            *(float4*)&f0[0] = *(const float4*)&v0p[0];
            *(float4*)&f0[4] = *(const float4*)&v0p[4];
            *(float4*)&f1[0] = *(const float4*)&v1p[0];
            *(float4*)&f1[4] = *(const float4*)&v1p[4];
#pragma unroll
            for (int j = 0; j < 8; ++j) {
                int hd = warp * 8 + j;
                char* base = asm_ + AV_OFF + hd * AROWB;
                *(uint32_t*)(base + lane * 4)       = hi_pair(f0[j], f1[j]);
                *(uint32_t*)(base + 128 + lane * 4) = lo_pair(f0[j], f1[j]);
            }
        }
        CPASYNC_WAIT0();          // K(ti) arrived
        __syncthreads();
        if (have) {               // K(ti+1) flies under compute
            cpK(ti + 1, p ^ 1);
            CPASYNC_COMMIT();
        }

        const uint32_t kb_base = smb + p * KBUF + kb_rel;

        // ---- S = Q K^T
        float s[8][4];
#pragma unroll
        for (int nt = 0; nt < 8; ++nt)
#pragma unroll
            for (int i = 0; i < 4; ++i) s[nt][i] = 0.0f;
#pragma unroll
        for (int ks = 0; ks < 4; ++ks) {
            uint32_t ah[4], al[4];
            LDMX4(ah[0], ah[1], ah[2], ah[3], a_base + ks * 32);
            LDMX4(al[0], al[1], al[2], al[3], a_base + ks * 32 + 128);
#pragma unroll
            for (int npp = 0; npp < 2; ++npp) {
                const int np0 = npp * 2, np1 = npp * 2 + 1;
                uint32_t bh0[4], bl0[4], bh1[4], bl1[4];
                LDMX4(bh0[0], bh0[1], bh0[2], bh0[3],
                      kb_base + np0 * (16 * AROWB) + ks * 32);
                LDMX4(bl0[0], bl0[1], bl0[2], bl0[3],
                      kb_base + np0 * (16 * AROWB) + ks * 32 + 128);
                LDMX4(bh1[0], bh1[1], bh1[2], bh1[3],
                      kb_base + np1 * (16 * AROWB) + ks * 32);
                LDMX4(bl1[0], bl1[1], bl1[2], bl1[3],
                      kb_base + np1 * (16 * AROWB) + ks * 32 + 128);
                MMA_BF16(s[2*np0],     ah, bh0[0], bh0[1]);
                MMA_BF16(s[2*np0 + 1], ah, bh0[2], bh0[3]);
                MMA_BF16(s[2*np1],     ah, bh1[0], bh1[1]);
                MMA_BF16(s[2*np1 + 1], ah, bh1[2], bh1[3]);
                MMA_BF16(s[2*np0],     al, bh0[0], bh0[1]);
                MMA_BF16(s[2*np0 + 1], al, bh0[2], bh0[3]);
                MMA_BF16(s[2*np1],     al, bh1[0], bh1[1]);
                MMA_BF16(s[2*np1 + 1], al, bh1[2], bh1[3]);
                MMA_BF16(s[2*np0],     ah, bl0[0], bl0[1]);
                MMA_BF16(s[2*np0 + 1], ah, bl0[2], bl0[3]);
                MMA_BF16(s[2*np1],     ah, bl1[0], bl1[1]);
                MMA_BF16(s[2*np1 + 1], ah, bl1[2], bl1[3]);
            }
        }

        // ---- online softmax (base 2)
#pragma unroll
        for (int r2 = 0; r2 < 2; ++r2) {
            float mx = -1e30f;
#pragma unroll
            for (int nt = 0; nt < 8; ++nt)
                mx = fmaxf(mx, fmaxf(s[nt][r2*2], s[nt][r2*2+1]));
#pragma unroll
            for (int off = 1; off <= 2; off <<= 1)
                mx = fmaxf(mx, __shfl_xor_sync(0xffffffffu, mx, off));
            float mnew = fmaxf(mrow[r2], mx);
            float corr = fexp2(mrow[r2] - mnew);
            float ps = 0.0f;
#pragma unroll
            for (int nt = 0; nt < 8; ++nt) {
                float p0 = fexp2(s[nt][r2*2]   - mnew);
                float p1 = fexp2(s[nt][r2*2+1] - mnew);
                s[nt][r2*2] = p0; s[nt][r2*2+1] = p1;
                ps += p0 + p1;
            }
#pragma unroll
            for (int off = 1; off <= 2; off <<= 1)
                ps += __shfl_xor_sync(0xffffffffu, ps, off);
            lrow[r2] = lrow[r2] * corr + ps;
            mrow[r2] = mnew;
#pragma unroll
            for (int nt = 0; nt < 8; ++nt) {
                acc_o[nt][r2*2]   *= corr;
                acc_o[nt][r2*2+1] *= corr;
            }
        }

        // ---- O += P V
#pragma unroll
        for (int kt = 0; kt < 4; ++kt) {
            uint32_t pah[4], pal[4];
            pah[0] = hi_pair(s[2*kt][0],   s[2*kt][1]);
            pah[1] = hi_pair(s[2*kt][2],   s[2*kt][3]);
            pah[2] = hi_pair(s[2*kt+1][0], s[2*kt+1][1]);
            pah[3] = hi_pair(s[2*kt+1][2], s[2*kt+1][3]);
            pal[0] = lo_pair(s[2*kt][0],   s[2*kt][1]);
            pal[1] = lo_pair(s[2*kt][2],   s[2*kt][3]);
            pal[2] = lo_pair(s[2*kt+1][0], s[2*kt+1][1]);
            pal[3] = lo_pair(s[2*kt+1][2], s[2*kt+1][3]);
#pragma unroll
            for (int npp = 0; npp < 2; ++npp) {
                const int np0 = npp * 2, np1 = npp * 2 + 1;
                uint32_t vh0[4], vl0[4], vh1[4], vl1[4];
                LDMX4(vh0[0], vh0[1], vh0[2], vh0[3],
                      vb_base + np0 * (16 * AROWB) + kt * 32);
                LDMX4(vl0[0], vl0[1], vl0[2], vl0[3],
                      vb_base + np0 * (16 * AROWB) + kt * 32 + 128);
                LDMX4(vh1[0], vh1[1], vh1[2], vh1[3],
                      vb_base + np1 * (16 * AROWB) + kt * 32);
                LDMX4(vl1[0], vl1[1], vl1[2], vl1[3],
                      vb_base + np1 * (16 * AROWB) + kt * 32 + 128);
                MMA_BF16(acc_o[2*np0],     pah, vh0[0], vh0[1]);
                MMA_BF16(acc_o[2*np0 + 1], pah, vh0[2], vh0[3]);
                MMA_BF16(acc_o[2*np1],     pah, vh1[0], vh1[1]);
                MMA_BF16(acc_o[2*np1 + 1], pah, vh1[2], vh1[3]);
                MMA_BF16(acc_o[2*np0],     pal, vh0[0], vh0[1]);
                MMA_BF16(acc_o[2*np0 + 1], pal, vh0[2], vh0[3]);
                MMA_BF16(acc_o[2*np1],     pal, vh1[0], vh1[1]);
                MMA_BF16(acc_o[2*np1 + 1], pal, vh1[2], vh1[3]);
                MMA_BF16(acc_o[2*np0],     pah, vl0[0], vl0[1]);
                MMA_BF16(acc_o[2*np0 + 1], pah, vl0[2], vl0[3]);
                MMA_BF16(acc_o[2*np1],     pah, vl1[0], vl1[1]);
                MMA_BF16(acc_o[2*np1 + 1], pah, vl1[2], vl1[3]);
            }
        }
        p ^= 1;
    }

    // ---- write ctx as pair-plane
    float inv0 = 1.0f / lrow[0];
    float inv1 = 1.0f / lrow[1];
#pragma unroll
    for (int r2 = 0; r2 < 2; ++r2) {
        int grow = b * N_ + q0 + warp * 16 + g + r2 * 8;
        float inv = r2 ? inv1 : inv0;
#pragma unroll
        for (int nt = 0; nt < 8; ++nt) {
            float v0 = acc_o[nt][r2*2]   * inv;
            float v1 = acc_o[nt][r2*2+1] * inv;
            int pidx = h * 32 + nt * 4 + t4;
            ctxP[(size_t)grow * 256 + pidx]       = hi_pair(v0, v1);
            ctxP[(size_t)grow * 256 + 128 + pidx] = lo_pair(v0, v1);
        }
    }
}

// ---------------------------------------------------------------------------
// mean-pool + classifier
// ---------------------------------------------------------------------------
__global__ __launch_bounds__(256) void pool_cls_kernel(
    const float* __restrict__ xm,
    const float* __restrict__ Wc,
    const float* __restrict__ bc,
    float* __restrict__ out)
{
    __shared__ float pooled[D_];
    const int b = blockIdx.x;
    const int t = threadIdx.x;
    float s = 0.0f;
    const float* p = xm + (size_t)b * N_ * D_ + t;
#pragma unroll 8
    for (int n = 0; n < N_; ++n) s += p[(size_t)n * D_];
    pooled[t] = s * (1.0f / (float)N_);
    __syncthreads();
    if (t < 2) {
        float a = bc[t];
        for (int c = 0; c < D_; ++c) a = fmaf(pooled[c], Wc[t * D_ + c], a);
        out[b * 2 + t] = a;
    }
}

// ---------------------------------------------------------------------------
// Launch
// ---------------------------------------------------------------------------
static void* symp(const void* s) {
    void* p = nullptr;
    cudaGetSymbolAddress(&p, s);
    return p;
}

extern "C" void kernel_launch(void* const* d_in, const int* in_sizes, int n_in,
                              void* d_out, int out_size)
{
    const float* x   = (const float*)d_in[0];
    const float* y   = (const float*)d_in[1];
    const float* Wr  = (const float*)d_in[3];
    const float* br  = (const float*)d_in[4];
    const float* Wf  = (const float*)d_in[5];
    const float* bf  = (const float*)d_in[6];
    const float* g_x = (const float*)d_in[7];
    const float* b_x = (const float*)d_in[8];
    const float* g_y = (const float*)d_in[9];
    const float* b_y = (const float*)d_in[10];
    const float* Wq  = (const float*)d_in[11];
    const float* bq  = (const float*)d_in[12];
    const float* Wk  = (const float*)d_in[13];
    const float* bk  = (const float*)d_in[14];
    const float* Wv  = (const float*)d_in[15];
    const float* bv  = (const float*)d_in[16];
    const float* Wo  = (const float*)d_in[17];
    const float* bo  = (const float*)d_in[18];
    const float* g_m = (const float*)d_in[19];
    const float* b_m = (const float*)d_in[20];
    const float* W1  = (const float*)d_in[21];
    const float* b1  = (const float*)d_in[22];
    const float* W2  = (const float*)d_in[23];
    const float* b2  = (const float*)d_in[24];
    const float* Wc  = (const float*)d_in[25];
    const float* bc  = (const float*)d_in[26];
    float* out = (float*)d_out;

    float*    xp   = (float*)symp(g_xp);
    float*    yp   = (float*)symp(g_yp);
    float*    vb_  = (float*)symp(g_v);
    float*    xres = (float*)symp(g_xres);
    float*    xmlp = (float*)symp(g_xmlp);
    float*    pe   = (float*)symp(g_pe);
    uint32_t* xpP  = (uint32_t*)symp(g_xpP);
    uint32_t* ypP  = (uint32_t*)symp(g_ypP);
    uint32_t* qP   = (uint32_t*)symp(g_qP);
    uint32_t* kP   = (uint32_t*)symp(g_kP);
    uint32_t* ctxP = (uint32_t*)symp(g_ctxP);
    uint32_t* xrsP = (uint32_t*)symp(g_xrsP);
    uint32_t* hidP = (uint32_t*)symp(g_hidP);
    uint32_t* wb   = (uint32_t*)symp(g_wbuf);

    static bool attr_set = false;
    if (!attr_set) {
        cudaFuncSetAttribute(attn_kernel,
                             cudaFuncAttributeMaxDynamicSharedMemorySize, ASM_TOT);
        cudaFuncSetAttribute(hmma_gemm_n128<0, 1>,
                             cudaFuncAttributeMaxDynamicSharedMemorySize, SM_TOT_S);
        cudaFuncSetAttribute(hmma_gemm_n128<1, 1>,
                             cudaFuncAttributeMaxDynamicSharedMemorySize, SM_TOT_S);
        cudaFuncSetAttribute(hmma_gemm_n128<2, 1>,
                             cudaFuncAttributeMaxDynamicSharedMemorySize, SM_TOT_S);
        cudaFuncSetAttribute(hmma_gemm_n128<4, 0>,
                             cudaFuncAttributeMaxDynamicSharedMemorySize, SM_TOT_S);
        attr_set = true;
    }

    dim3 gs(M_ / 64 * 2);  // 1024 CTAs
    dim3 bb(256);
    dim3 lg(M_ / 8);       // 4096 CTAs (LN)

    prep_kernel<<<(WB_TOT + N_ * D_ + 255) / 256, 256>>>(Wr, Wf, Wq, Wk, Wv, Wo, W1, W2);

    // xp = x @ Wr^T + br + pe ; LN in place + pairs
    hmma_gemm_n128<4, 0><<<gs, bb, SM_TOT_S>>>(x, nullptr, 769, 25, wb + WR_OFF, 800, 0,
        br, nullptr, nullptr, pe, 1.0f, xp, nullptr, nullptr, nullptr);
    ln_kernel<<<lg, bb>>>(xp, g_x, b_x, 1, xpP);
    // yp = y @ Wf^T + bf + pe ; LN -> pairs only
    hmma_gemm_n128<4, 0><<<gs, bb, SM_TOT_S>>>(y, nullptr, 674, 22, wb + WF_OFF, 704, 0,
        bf, nullptr, nullptr, pe, 1.0f, yp, nullptr, nullptr, nullptr);
    ln_kernel<<<lg, bb>>>(yp, g_y, b_y, 0, ypP);
    // q (scaled pairs)
    hmma_gemm_n128<0, 1><<<gs, bb, SM_TOT_S>>>(nullptr, xpP, 256, 8, wb + WQ_OFF, 256, 0,
        bq, nullptr, nullptr, nullptr, QSCALE, nullptr, nullptr, qP, nullptr);
    // k (pairs) + v (fp32) fused
    hmma_gemm_n128<0, 1><<<dim3(M_ / 64 * 2, 2), bb, SM_TOT_S>>>(nullptr, ypP, 256, 8,
        wb + WK_OFF, 256, 256 * 256,
        bk, bv, nullptr, nullptr, 1.0f, nullptr, vb_, kP, nullptr);
    // attention (K double-buffered, V single)
    dim3 ag(N_ / 128, B_ * H_);
    attn_kernel<<<ag, bb, ASM_TOT>>>(qP, kP, vb_, ctxP);
    // xres = xp + ctx @ Wo^T + bo ; LN in place + pairs
    hmma_gemm_n128<2, 1><<<gs, bb, SM_TOT_S>>>(nullptr, ctxP, 256, 8, wb + WO_OFF, 256, 0,
        bo, nullptr, xp, nullptr, 1.0f, xres, nullptr, nullptr, nullptr);
    ln_kernel<<<lg, bb>>>(xres, g_m, b_m, 1, xrsP);
    // hid = relu(xres @ W1^T + b1) -> pairs only
    hmma_gemm_n128<1, 1><<<gs, bb, SM_TOT_S>>>(nullptr, xrsP, 256, 8, wb + W1_OFF, 256, 0,
        b1, nullptr, nullptr, nullptr, 1.0f, nullptr, nullptr, hidP, nullptr);
    // xmlp = xres + hid @ W2^T + b2
    hmma_gemm_n128<2, 1><<<gs, bb, SM_TOT_S>>>(nullptr, hidP, 256, 8, wb + W2_OFF, 256, 0,
        b2, nullptr, xres, nullptr, 1.0f, xmlp, nullptr, nullptr, nullptr);
    // pool + classifier
    pool_cls_kernel<<<B_, bb>>>(xmlp, Wc, bc, out);
}